// round 16
// baseline (speedup 1.0000x reference)
#include <cuda_runtime.h>
#include <stdint.h>
#include <math.h>

// Problem constants
#define BB 2
#define TT 2048
#define CCH 512
#define HH 8
#define DD 64
#define NROWS (BB*TT)   // 4096
#define C3 (3*CCH)      // 1536

// ---------------- scratch ----------------
__device__ float g_h   [NROWS*CCH];
__device__ float g_qkv [NROWS*C3];
__device__ float g_att0[NROWS*CCH];
__device__ float g_att1[NROWS*CCH];
__device__ float g_y   [NROWS*CCH];
__device__ float g_y2  [NROWS*CCH];
__device__ float g_h2  [NROWS*CCH];
__device__ float g_fc  [NROWS*4*CCH];
// pre-rounded, TRANSPOSED weights: Wt[n][k] = tf32(W[k][n])
__device__ float g_wattn[C3*CCH];
__device__ float g_wself[CCH*CCH];
__device__ float g_wproj[CCH*CCH];
__device__ float g_wfc  [4*CCH*CCH];
__device__ float g_wfcp [CCH*4*CCH];

// ---------------- helpers ----------------
__device__ __forceinline__ float cvt_tf32(float x) {
    unsigned u; asm("cvt.rna.tf32.f32 %0, %1;" : "=r"(u) : "f"(x));
    return __uint_as_float(u);
}

__device__ __forceinline__ void mma_tf32(float& c0, float& c1, float& c2, float& c3,
                                         unsigned a0, unsigned a1, unsigned a2, unsigned a3,
                                         unsigned b0, unsigned b1) {
    asm volatile("mma.sync.aligned.m16n8k8.row.col.f32.tf32.tf32.f32 "
                 "{%0,%1,%2,%3}, {%4,%5,%6,%7}, {%8,%9}, {%0,%1,%2,%3};"
                 : "+f"(c0), "+f"(c1), "+f"(c2), "+f"(c3)
                 : "r"(a0), "r"(a1), "r"(a2), "r"(a3), "r"(b0), "r"(b1));
}

__device__ __forceinline__ void ldsm4(unsigned& r0, unsigned& r1, unsigned& r2, unsigned& r3,
                                      unsigned addr) {
    asm volatile("ldmatrix.sync.aligned.m8n8.x4.shared.b16 {%0,%1,%2,%3}, [%4];"
                 : "=r"(r0), "=r"(r1), "=r"(r2), "=r"(r3) : "r"(addr));
}

__device__ __forceinline__ unsigned smem_u32(const void* p) {
    return (unsigned)__cvta_generic_to_shared(p);
}

__device__ __forceinline__ void cp16(float* smem_dst, const float* g_src) {
    unsigned s = (unsigned)__cvta_generic_to_shared(smem_dst);
    asm volatile("cp.async.cg.shared.global [%0], [%1], 16;" :: "r"(s), "l"(g_src));
}
__device__ __forceinline__ void cp_commit() {
    asm volatile("cp.async.commit_group;" ::: "memory");
}
__device__ __forceinline__ void cp_wait0() {
    asm volatile("cp.async.wait_group 0;" ::: "memory");
}

// sigmoid via MUFU
__device__ __forceinline__ float sigmoid_mufu(float x) {
    float e;
    asm("ex2.approx.f32 %0, %1;" : "=f"(e) : "f"(x * -1.4426950408889634f));
    float r;
    asm("rcp.approx.f32 %0, %1;" : "=f"(r) : "f"(1.0f + e));
    return r;
}

// ---------------- weight transpose + tf32 round ----------------
__global__ __launch_bounds__(256) void tcvt(const float* __restrict__ W,
                                            float* __restrict__ Wt, int K, int N)
{
    __shared__ float t[32][33];
    int n0 = blockIdx.x * 32, k0 = blockIdx.y * 32;
    int tx = threadIdx.x & 31, ty = threadIdx.x >> 5;   // 32x8
    #pragma unroll
    for (int j = 0; j < 4; j++)
        t[ty + j*8][tx] = W[(size_t)(k0 + ty + j*8) * N + n0 + tx];
    __syncthreads();
    #pragma unroll
    for (int j = 0; j < 4; j++)
        Wt[(size_t)(n0 + ty + j*8) * K + k0 + tx] = cvt_tf32(t[tx][ty + j*8]);
}

// ---------------- LayerNorm ----------------
__global__ __launch_bounds__(128) void ln_kernel(const float* __restrict__ x,
                                                 const float* __restrict__ g,
                                                 const float* __restrict__ bta,
                                                 float* __restrict__ out)
{
    int row = blockIdx.x;
    int t = threadIdx.x;
    const float4* xr = (const float4*)(x + (size_t)row * CCH);
    float4 v = xr[t];
    float s  = v.x + v.y + v.z + v.w;
    float s2 = v.x*v.x + v.y*v.y + v.z*v.z + v.w*v.w;
    #pragma unroll
    for (int o = 16; o; o >>= 1) {
        s  += __shfl_xor_sync(0xffffffffu, s,  o);
        s2 += __shfl_xor_sync(0xffffffffu, s2, o);
    }
    __shared__ float ss[4], ss2[4];
    int w = t >> 5, l = t & 31;
    if (l == 0) { ss[w] = s; ss2[w] = s2; }
    __syncthreads();
    s  = ss[0]  + ss[1]  + ss[2]  + ss[3];
    s2 = ss2[0] + ss2[1] + ss2[2] + ss2[3];
    float m   = s  * (1.0f/512.0f);
    float var = s2 * (1.0f/512.0f) - m*m;
    float r   = rsqrtf(var + 1e-5f);
    float4 gv = ((const float4*)g)[t];
    float4 bv = ((const float4*)bta)[t];
    float4 o4;
    o4.x = cvt_tf32((v.x - m) * r * gv.x + bv.x);
    o4.y = cvt_tf32((v.y - m) * r * gv.y + bv.y);
    o4.z = cvt_tf32((v.z - m) * r * gv.z + bv.z);
    o4.w = cvt_tf32((v.w - m) * r * gv.w + bv.w);
    ((float4*)(out + (size_t)row * CCH))[t] = o4;
}

// ---------------- TF32 GEMM: BM=128 BN=64 BK=32, 128 thr, 4 CTAs/SM ----------------
// A and B BOTH K-major; A- and B-fragments via ldmatrix.x4 (one B ldsm -> 2 n8 frags).
#define G_AS_STRIDE 36
#define G_BS_STRIDE 36
#define G_AS_SZ (128*G_AS_STRIDE)
#define G_BS_SZ (64*G_BS_STRIDE)
#define G_SMEM ((2*G_AS_SZ + 2*G_BS_SZ)*4)   // 55296 B

template<bool HAS_ADD, bool HAS_ADD2, bool GELU_EPI, bool ROUND_OUT>
__global__ __launch_bounds__(128, 4) void gemm_tf32(
    const float* __restrict__ A, const float* __restrict__ Wt,
    const float* __restrict__ bias,
    const float* __restrict__ addm, const float* __restrict__ addm2,
    float* __restrict__ Cmat, int M, int N, int K)
{
    extern __shared__ float sh[];
    float* As = sh;
    float* Bs = sh + 2*G_AS_SZ;

    const int tid  = threadIdx.x;
    const int warp = tid >> 5, lane = tid & 31;
    const int gid  = lane >> 2, tig = lane & 3;
    const int lg   = lane >> 3, lw = lane & 7;
    const int wm   = (warp >> 1) * 64;
    const int wn   = (warp & 1) * 32;
    const int bm   = blockIdx.y * 128, bn = blockIdx.x * 64;

    const int ar = tid >> 3, ac = (tid & 7) * 4;   // loader: 16 rows/pass, 8 thr/row

    const float* Ag = A  + (size_t)bm * K;
    const float* Bg = Wt + (size_t)bn * K;

    const unsigned as_u = smem_u32(As);
    const unsigned bs_u = smem_u32(Bs);
    const unsigned gA_off = ((wm + (lg & 1)*8 + lw) * G_AS_STRIDE + (lg >> 1)*4) * 4u;
    const unsigned gB_off = ((wn + (lg & 1)*8 + lw) * G_BS_STRIDE + (lg >> 1)*4) * 4u;

    float acc[4][4][4] = {};
    const int nk = K >> 5;

    // stage 0: A 128 rows (8 passes), B 64 rows (4 passes)
    #pragma unroll
    for (int i = 0; i < 8; i++)
        cp16(As + (ar + i*16)*G_AS_STRIDE + ac, Ag + (size_t)(ar + i*16) * K + ac);
    #pragma unroll
    for (int i = 0; i < 4; i++)
        cp16(Bs + (ar + i*16)*G_BS_STRIDE + ac, Bg + (size_t)(ar + i*16) * K + ac);
    cp_commit();

    for (int kt = 0; kt < nk; kt++) {
        cp_wait0();
        __syncthreads();
        if (kt + 1 < nk) {
            int k0 = (kt + 1) << 5;
            float* asn = As + ((kt + 1) & 1) * G_AS_SZ;
            float* bsn = Bs + ((kt + 1) & 1) * G_BS_SZ;
            #pragma unroll
            for (int i = 0; i < 8; i++)
                cp16(asn + (ar + i*16)*G_AS_STRIDE + ac, Ag + (size_t)(ar + i*16) * K + k0 + ac);
            #pragma unroll
            for (int i = 0; i < 4; i++)
                cp16(bsn + (ar + i*16)*G_BS_STRIDE + ac, Bg + (size_t)(ar + i*16) * K + k0 + ac);
            cp_commit();
        }
        const unsigned as_b = as_u + (unsigned)((kt & 1) * G_AS_SZ * 4) + gA_off;
        const unsigned bs_b = bs_u + (unsigned)((kt & 1) * G_BS_SZ * 4) + gB_off;

        #pragma unroll
        for (int ks = 0; ks < 4; ks++) {
            unsigned af[4][4], bf[4][2];
            #pragma unroll
            for (int mt = 0; mt < 4; mt++)
                ldsm4(af[mt][0], af[mt][1], af[mt][2], af[mt][3],
                      as_b + (unsigned)((mt*16*G_AS_STRIDE + ks*8) * 4));
            // one ldsm4 per 16 n-rows covers 2 n8 fragments
            {
                unsigned m0, m1, m2, m3;
                ldsm4(m0, m1, m2, m3, bs_b + (unsigned)((ks*8) * 4));
                bf[0][0] = m0; bf[0][1] = m2;
                bf[1][0] = m1; bf[1][1] = m3;
                ldsm4(m0, m1, m2, m3, bs_b + (unsigned)((16*G_BS_STRIDE + ks*8) * 4));
                bf[2][0] = m0; bf[2][1] = m2;
                bf[3][0] = m1; bf[3][1] = m3;
            }
            #pragma unroll
            for (int mt = 0; mt < 4; mt++)
                #pragma unroll
                for (int nt = 0; nt < 4; nt++)
                    mma_tf32(acc[mt][nt][0], acc[mt][nt][1], acc[mt][nt][2], acc[mt][nt][3],
                             af[mt][0], af[mt][1], af[mt][2], af[mt][3],
                             bf[nt][0], bf[nt][1]);
        }
    }

    #pragma unroll
    for (int mt = 0; mt < 4; mt++) {
        int r0 = bm + wm + mt*16 + gid;
        #pragma unroll
        for (int nt = 0; nt < 4; nt++) {
            int c0 = bn + wn + nt*8 + 2*tig;
            float2 bv = *(const float2*)(bias + c0);
            float v0 = acc[mt][nt][0] + bv.x;
            float v1 = acc[mt][nt][1] + bv.y;
            float v2 = acc[mt][nt][2] + bv.x;
            float v3 = acc[mt][nt][3] + bv.y;
            size_t o0 = (size_t)r0 * N + c0;
            size_t o1 = (size_t)(r0 + 8) * N + c0;
            if (HAS_ADD) {
                float2 d0 = *(const float2*)(addm + o0);
                float2 d1 = *(const float2*)(addm + o1);
                v0 += d0.x; v1 += d0.y; v2 += d1.x; v3 += d1.y;
            }
            if (HAS_ADD2) {
                float2 d0 = *(const float2*)(addm2 + o0);
                float2 d1 = *(const float2*)(addm2 + o1);
                v0 += d0.x; v1 += d0.y; v2 += d1.x; v3 += d1.y;
            }
            if (GELU_EPI) {
                v0 = 0.5f * v0 * (1.0f + erff(v0 * 0.70710678118654752f));
                v1 = 0.5f * v1 * (1.0f + erff(v1 * 0.70710678118654752f));
                v2 = 0.5f * v2 * (1.0f + erff(v2 * 0.70710678118654752f));
                v3 = 0.5f * v3 * (1.0f + erff(v3 * 0.70710678118654752f));
            }
            if (ROUND_OUT) {
                v0 = cvt_tf32(v0); v1 = cvt_tf32(v1);
                v2 = cvt_tf32(v2); v3 = cvt_tf32(v3);
            }
            *(float2*)(Cmat + o0) = make_float2(v0, v1);
            *(float2*)(Cmat + o1) = make_float2(v2, v3);
        }
    }
}

// ---------------- attention: mt=2 (32 t-rows/warp), 128 thr, s-split x2 (R14) ----------------
#define A_KS_STRIDE 68
#define A_VS_STRIDE 72
#define A_SS_STRIDE 36
#define A_KS_SZ (64*A_KS_STRIDE)
#define A_VS_SZ (64*A_VS_STRIDE)
#define A_SMEM ((2*A_KS_SZ + 2*A_VS_SZ + 128*A_SS_STRIDE)*4)   // 90112 B
#define NKT (TT/64)

__global__ __launch_bounds__(128, 2) void attn_tf32(const float* __restrict__ qkv,
                                                    const float* __restrict__ coul,
                                                    float* __restrict__ yatt0,
                                                    float* __restrict__ yatt1)
{
    extern __shared__ float sh[];
    float* Ks = sh;
    float* Vs = sh + 2*A_KS_SZ;
    float* Ss = Vs + 2*A_VS_SZ;

    const int bh = blockIdx.x;
    const int b = bh >> 3, h = bh & 7;
    const int ttile = blockIdx.y >> 1;
    const int shalf = blockIdx.y & 1;
    const int t0 = ttile * 128;
    const int kt0 = shalf * (NKT/2), kt1 = kt0 + (NKT/2);
    const int tid = threadIdx.x, warp = tid >> 5, lane = tid & 31;
    const int gid = lane >> 2, tig = lane & 3;
    const int lg = lane >> 3, lw = lane & 7;
    const int lr = tid >> 4, lc = (tid & 15) * 4;
    const int rw = warp * 32;

    const unsigned ks_u = smem_u32(Ks);
    const unsigned ss_u = smem_u32(Ss);
    const unsigned qkB_off = (((lg >> 1)*8 + lw) * A_KS_STRIDE + (lg & 1)*4) * 4u;
    const unsigned pvA0 = ((rw + (lg & 1)*8 + lw) * A_SS_STRIDE + (lg >> 1)*4) * 4u;
    const unsigned pvA1 = pvA0 + (unsigned)(16 * A_SS_STRIDE * 4);

    float qf[2][8][4];
    #pragma unroll
    for (int mt = 0; mt < 2; mt++) {
        const float* q0 = qkv + (size_t)(b*TT + t0 + rw + mt*16 + gid) * C3 + h*DD;
        #pragma unroll
        for (int kd = 0; kd < 8; kd++) {
            qf[mt][kd][0] = q0[kd*8 + tig]            * 0.125f;
            qf[mt][kd][1] = q0[8*C3 + kd*8 + tig]     * 0.125f;
            qf[mt][kd][2] = q0[kd*8 + tig + 4]        * 0.125f;
            qf[mt][kd][3] = q0[8*C3 + kd*8 + tig + 4] * 0.125f;
        }
    }

    float yacc[2][8][4];
    #pragma unroll
    for (int mt = 0; mt < 2; mt++)
        #pragma unroll
        for (int i = 0; i < 8; i++)
            { yacc[mt][i][0]=0.f; yacc[mt][i][1]=0.f; yacc[mt][i][2]=0.f; yacc[mt][i][3]=0.f; }

    const float* cb[2];
    cb[0] = coul + (size_t)b * TT * TT + (size_t)(t0 + rw + gid) * TT;
    cb[1] = cb[0] + (size_t)16 * TT;
    const float* kbase = qkv + (size_t)(b*TT) * C3 + CCH + h*DD;

    {
        const float* k0p = kbase + (size_t)(kt0 * 64) * C3;
        float* kd_ = Ks + (kt0 & 1) * A_KS_SZ;
        float* vd_ = Vs + (kt0 & 1) * A_VS_SZ;
        #pragma unroll
        for (int i = 0; i < 8; i++) {
            int r = lr + i*8;
            cp16(kd_ + r*A_KS_STRIDE + lc, k0p + (size_t)r * C3 + lc);
            cp16(vd_ + r*A_VS_STRIDE + lc, k0p + CCH + (size_t)r * C3 + lc);
        }
        cp_commit();
    }

    for (int kt = kt0; kt < kt1; kt++) {
        cp_wait0();
        __syncthreads();
        if (kt + 1 < kt1) {
            const float* kn = kbase + (size_t)((kt + 1) * 64) * C3;
            float* kd_ = Ks + ((kt + 1) & 1) * A_KS_SZ;
            float* vd_ = Vs + ((kt + 1) & 1) * A_VS_SZ;
            #pragma unroll
            for (int i = 0; i < 8; i++) {
                int r = lr + i*8;
                cp16(kd_ + r*A_KS_STRIDE + lc, kn + (size_t)r * C3 + lc);
                cp16(vd_ + r*A_VS_STRIDE + lc, kn + CCH + (size_t)r * C3 + lc);
            }
            cp_commit();
        }
        const unsigned ksb_u = ks_u + (unsigned)((kt & 1) * A_KS_SZ * 4) + qkB_off;
        const float* vsb = Vs + (kt & 1) * A_VS_SZ;
        const int s0 = kt * 64;

        #pragma unroll
        for (int hf = 0; hf < 2; hf++) {
            float2 c0[2][4], c1[2][4];
            #pragma unroll
            for (int mt = 0; mt < 2; mt++)
                #pragma unroll
                for (int nt = 0; nt < 4; nt++) {
                    int sc = s0 + hf*32 + nt*8 + 2*tig;
                    c0[mt][nt] = *(const float2*)(cb[mt] + sc);
                    c1[mt][nt] = *(const float2*)(cb[mt] + 8*TT + sc);
                }

            float sacc[2][4][4];
            #pragma unroll
            for (int mt = 0; mt < 2; mt++)
                #pragma unroll
                for (int i = 0; i < 4; i++)
                    { sacc[mt][i][0]=0.f; sacc[mt][i][1]=0.f; sacc[mt][i][2]=0.f; sacc[mt][i][3]=0.f; }
            #pragma unroll
            for (int kd = 0; kd < 8; kd++) {
                #pragma unroll
                for (int p = 0; p < 2; p++) {
                    unsigned b0e, b1e, b0o, b1o;
                    ldsm4(b0e, b1e, b0o, b1o,
                          ksb_u + (unsigned)(((hf*32 + p*16)*A_KS_STRIDE + kd*8) * 4));
                    #pragma unroll
                    for (int mt = 0; mt < 2; mt++) {
                        mma_tf32(sacc[mt][2*p][0], sacc[mt][2*p][1], sacc[mt][2*p][2], sacc[mt][2*p][3],
                                 __float_as_uint(qf[mt][kd][0]), __float_as_uint(qf[mt][kd][1]),
                                 __float_as_uint(qf[mt][kd][2]), __float_as_uint(qf[mt][kd][3]),
                                 b0e, b1e);
                        mma_tf32(sacc[mt][2*p+1][0], sacc[mt][2*p+1][1], sacc[mt][2*p+1][2], sacc[mt][2*p+1][3],
                                 __float_as_uint(qf[mt][kd][0]), __float_as_uint(qf[mt][kd][1]),
                                 __float_as_uint(qf[mt][kd][2]), __float_as_uint(qf[mt][kd][3]),
                                 b0o, b1o);
                    }
                }
            }

            #pragma unroll
            for (int mt = 0; mt < 2; mt++)
                #pragma unroll
                for (int nt = 0; nt < 4; nt++) {
                    float* sp = Ss + (rw + mt*16 + gid)*A_SS_STRIDE + nt*8 + 2*tig;
                    *(float2*)(sp) = make_float2(
                        cvt_tf32(sigmoid_mufu(sacc[mt][nt][0]) * c0[mt][nt].x),
                        cvt_tf32(sigmoid_mufu(sacc[mt][nt][1]) * c0[mt][nt].y));
                    *(float2*)(sp + 8*A_SS_STRIDE) = make_float2(
                        cvt_tf32(sigmoid_mufu(sacc[mt][nt][2]) * c1[mt][nt].x),
                        cvt_tf32(sigmoid_mufu(sacc[mt][nt][3]) * c1[mt][nt].y));
                }
            __syncwarp();

            #pragma unroll
            for (int ks = 0; ks < 4; ks++) {
                unsigned a0[2], a1[2], a2[2], a3[2];
                ldsm4(a0[0], a1[0], a2[0], a3[0], ss_u + pvA0 + (unsigned)(ks*8*4));
                ldsm4(a0[1], a1[1], a2[1], a3[1], ss_u + pvA1 + (unsigned)(ks*8*4));
                #pragma unroll
                for (int nt = 0; nt < 8; nt++) {
                    const float* bp = vsb + (hf*32 + ks*8 + tig)*A_VS_STRIDE + nt*8 + gid;
                    unsigned bv0 = __float_as_uint(bp[0]);
                    unsigned bv1 = __float_as_uint(bp[4*A_VS_STRIDE]);
                    mma_tf32(yacc[0][nt][0], yacc[0][nt][1], yacc[0][nt][2], yacc[0][nt][3],
                             a0[0], a1[0], a2[0], a3[0], bv0, bv1);
                    mma_tf32(yacc[1][nt][0], yacc[1][nt][1], yacc[1][nt][2], yacc[1][nt][3],
                             a0[1], a1[1], a2[1], a3[1], bv0, bv1);
                }
            }
            __syncwarp();
        }
    }

    float* ybuf = shalf ? yatt1 : yatt0;
    #pragma unroll
    for (int mt = 0; mt < 2; mt++) {
        float* ob = ybuf + (size_t)(b*TT + t0 + rw + mt*16 + gid) * CCH + h*DD;
        #pragma unroll
        for (int nt = 0; nt < 8; nt++) {
            int c = nt*8 + 2*tig;
            *(float2*)(ob + c)         = make_float2(yacc[mt][nt][0], yacc[mt][nt][1]);
            *(float2*)(ob + 8*CCH + c) = make_float2(yacc[mt][nt][2], yacc[mt][nt][3]);
        }
    }
}

// ---------------- launch ----------------
extern "C" void kernel_launch(void* const* d_in, const int* in_sizes, int n_in,
                              void* d_out, int out_size)
{
    const float* x      = (const float*)d_in[0];
    const float* coul   = (const float*)d_in[2];
    const float* ln1g   = (const float*)d_in[3];
    const float* ln1b   = (const float*)d_in[4];
    const float* w_attn = (const float*)d_in[5];
    const float* b_attn = (const float*)d_in[6];
    const float* w_self = (const float*)d_in[7];
    const float* b_self = (const float*)d_in[8];
    const float* w_proj = (const float*)d_in[9];
    const float* b_proj = (const float*)d_in[10];
    const float* ln2g   = (const float*)d_in[11];
    const float* ln2b   = (const float*)d_in[12];
    const float* w_fc   = (const float*)d_in[13];
    const float* b_fc   = (const float*)d_in[14];
    const float* w_fcp  = (const float*)d_in[15];
    const float* b_fcp  = (const float*)d_in[16];
    float* out = (float*)d_out;

    float *h, *qkvp, *att0, *att1, *yp, *y2p, *h2p, *fcp;
    float *wattn, *wself, *wproj, *wfc, *wfcp;
    cudaGetSymbolAddress((void**)&h,    g_h);
    cudaGetSymbolAddress((void**)&qkvp, g_qkv);
    cudaGetSymbolAddress((void**)&att0, g_att0);
    cudaGetSymbolAddress((void**)&att1, g_att1);
    cudaGetSymbolAddress((void**)&yp,   g_y);
    cudaGetSymbolAddress((void**)&y2p,  g_y2);
    cudaGetSymbolAddress((void**)&h2p,  g_h2);
    cudaGetSymbolAddress((void**)&fcp,  g_fc);
    cudaGetSymbolAddress((void**)&wattn, g_wattn);
    cudaGetSymbolAddress((void**)&wself, g_wself);
    cudaGetSymbolAddress((void**)&wproj, g_wproj);
    cudaGetSymbolAddress((void**)&wfc,   g_wfc);
    cudaGetSymbolAddress((void**)&wfcp,  g_wfcp);

    cudaFuncSetAttribute((const void*)gemm_tf32<false,false,false,true>,  cudaFuncAttributeMaxDynamicSharedMemorySize, G_SMEM);
    cudaFuncSetAttribute((const void*)gemm_tf32<false,false,true,true>,   cudaFuncAttributeMaxDynamicSharedMemorySize, G_SMEM);
    cudaFuncSetAttribute((const void*)gemm_tf32<true,true,false,true>,    cudaFuncAttributeMaxDynamicSharedMemorySize, G_SMEM);
    cudaFuncSetAttribute((const void*)gemm_tf32<false,false,false,false>, cudaFuncAttributeMaxDynamicSharedMemorySize, G_SMEM);
    cudaFuncSetAttribute(attn_tf32, cudaFuncAttributeMaxDynamicSharedMemorySize, A_SMEM);

    // 0) transpose + tf32-round weights: Wt[n][k]
    tcvt<<<dim3(48,16), 256>>>(w_attn, wattn, CCH, C3);
    tcvt<<<dim3(16,16), 256>>>(w_self, wself, CCH, CCH);
    tcvt<<<dim3(16,16), 256>>>(w_proj, wproj, CCH, CCH);
    tcvt<<<dim3(64,16), 256>>>(w_fc,   wfc,   CCH, 4*CCH);
    tcvt<<<dim3(16,64), 256>>>(w_fcp,  wfcp,  4*CCH, CCH);

    // 1) h = LN1(x)
    ln_kernel<<<NROWS, 128>>>(x, ln1g, ln1b, h);
    // 2) qkv = h @ w_attn + b_attn
    gemm_tf32<false,false,false,true><<<dim3(24,32), 128, G_SMEM>>>(h, wattn, b_attn, nullptr, nullptr, qkvp, NROWS, C3, CCH);
    // 3) attention, s-split x2, mt=2 warps
    attn_tf32<<<dim3(BB*HH, (TT/128)*2), 128, A_SMEM>>>(qkvp, coul, att0, att1);
    // 4) y = att0 + att1 + h @ w_self + b_self
    gemm_tf32<true,true,false,true><<<dim3(8,32), 128, G_SMEM>>>(h, wself, b_self, att0, att1, yp, NROWS, CCH, CCH);
    // 5) y2 = y @ w_proj + b_proj
    gemm_tf32<false,false,false,false><<<dim3(8,32), 128, G_SMEM>>>(yp, wproj, b_proj, nullptr, nullptr, y2p, NROWS, CCH, CCH);
    // 6) h2 = LN2(y2)
    ln_kernel<<<NROWS, 128>>>(y2p, ln2g, ln2b, h2p);
    // 7) fc = gelu(h2 @ w_fc + b_fc)
    gemm_tf32<false,false,true,true><<<dim3(32,32), 128, G_SMEM>>>(h2p, wfc, b_fc, nullptr, nullptr, fcp, NROWS, 4*CCH, CCH);
    // 8) out = fc @ w_fc_proj + b_fc_proj
    gemm_tf32<false,false,false,false><<<dim3(8,32), 128, G_SMEM>>>(fcp, wfcp, b_fcp, nullptr, nullptr, out, NROWS, CCH, 4*CCH);
}